// round 5
// baseline (speedup 1.0000x reference)
#include <cuda_runtime.h>
#include <cstdint>

#define BB 16
#define NN 1024
#define DD 256
#define HH 4
#define FF 64
#define HF 256

#define TI 64
#define TJ 16
#define NJT (NN / TJ)
#define ADJ_STR (TI + 1)           // 65: conflict-decorrelated transpose store
#define NS_J 68                    // ii-stride (TI=64 + 4 pad, keeps 16B align)
#define NS_H (TJ * NS_J + 8)       // 1096: per-head stride, shifts banks by 8

// Scratch (no cudaMalloc allowed): h = x@W, and per-(b,n,h) exp factor packs
__device__ float  g_h[BB * NN * HF];                 // 16 MB
__device__ float4 g_es[BB * NN * HH];                // (s, e^s, e^{0.2s}, -)
__device__ float4 g_ed[BB * NN * HH];                // (d, e^d, e^{0.2d}, -)

// ---------------- K1: h[b,n,hf] = sum_d x[b,n,d] * W[d,hf] ----------------
// M=16384, K=256, N=256. 64x64 block tile, 16 k-slab, 4x4 microtile.
__global__ __launch_bounds__(256) void k1_gemm(const float* __restrict__ X,
                                               const float* __restrict__ Wm) {
    __shared__ float As[16][68];   // transposed A slab, padded
    __shared__ float Bs[16][64];
    const int t  = threadIdx.x;
    const int m0 = blockIdx.y << 6;
    const int n0 = blockIdx.x << 6;
    const int tx = t & 15, ty = t >> 4;
    float acc[4][4];
#pragma unroll
    for (int r = 0; r < 4; r++)
#pragma unroll
        for (int q = 0; q < 4; q++) acc[r][q] = 0.f;

    for (int k0 = 0; k0 < DD; k0 += 16) {
        {
            const int arow = t >> 2, ac = (t & 3) << 2;
            float4 av = *(const float4*)&X[(size_t)(m0 + arow) * DD + k0 + ac];
            As[ac + 0][arow] = av.x;
            As[ac + 1][arow] = av.y;
            As[ac + 2][arow] = av.z;
            As[ac + 3][arow] = av.w;
            const int brow = t >> 4, bc = (t & 15) << 2;
            *(float4*)&Bs[brow][bc] =
                *(const float4*)&Wm[(size_t)(k0 + brow) * HF + n0 + bc];
        }
        __syncthreads();
#pragma unroll
        for (int k = 0; k < 16; k++) {
            float4 a = *(float4*)&As[k][ty << 2];
            float4 b = *(float4*)&Bs[k][tx << 2];
            acc[0][0] += a.x * b.x; acc[0][1] += a.x * b.y; acc[0][2] += a.x * b.z; acc[0][3] += a.x * b.w;
            acc[1][0] += a.y * b.x; acc[1][1] += a.y * b.y; acc[1][2] += a.y * b.z; acc[1][3] += a.y * b.w;
            acc[2][0] += a.z * b.x; acc[2][1] += a.z * b.y; acc[2][2] += a.z * b.z; acc[2][3] += a.z * b.w;
            acc[3][0] += a.w * b.x; acc[3][1] += a.w * b.y; acc[3][2] += a.w * b.z; acc[3][3] += a.w * b.w;
        }
        __syncthreads();
    }
#pragma unroll
    for (int r = 0; r < 4; r++) {
        float4 v = make_float4(acc[r][0], acc[r][1], acc[r][2], acc[r][3]);
        *(float4*)&g_h[(size_t)(m0 + (ty << 2) + r) * HF + n0 + (tx << 2)] = v;
    }
}

// ------- K2: per (b,n,h): s = h . a_src, d = h . a_dst, plus exp packs ------
__global__ __launch_bounds__(256) void k2_stats(const float* __restrict__ a_src,
                                                const float* __restrict__ a_dst) {
    const int gw   = (blockIdx.x * blockDim.x + threadIdx.x) >> 5; // (b*N+n)*H + h
    const int lane = threadIdx.x & 31;
    const int h    = gw & 3;
    const int bn   = gw >> 2;
    const float* hp = &g_h[(size_t)bn * HF + h * FF];
    const float v0 = hp[lane], v1 = hp[lane + 32];
    float s = v0 * a_src[h * FF + lane] + v1 * a_src[h * FF + lane + 32];
    float d = v0 * a_dst[h * FF + lane] + v1 * a_dst[h * FF + lane + 32];
#pragma unroll
    for (int o = 16; o > 0; o >>= 1) {
        s += __shfl_xor_sync(0xffffffffu, s, o);
        d += __shfl_xor_sync(0xffffffffu, d, o);
    }
    if (lane == 0) {
        g_es[gw] = make_float4(s, expf(s), expf(0.2f * s), 0.f);
        g_ed[gw] = make_float4(d, expf(d), expf(0.2f * d), 0.f);
    }
}

// ---- K3: fused masked softmax + aggregation as on-the-fly-A GEMM ----
// Block = (batch b, 64 target rows). Loop j in tiles of 16:
//   phase 1: n[ii,j,h] = mask ? ((d+s>=0) ? e^d*e^s : e^.2d*e^.2s) : 0 ; Z += n
//   phase 2: acc[ii, hf] += n[ii,j,head(hf)] * h[j,hf]   (8x8 reg microtile)
// Epilogue: out = acc / Z + bias.
__global__ __launch_bounds__(256, 2) void k3_agg(const float* __restrict__ adj,
                                                 const float* __restrict__ bias,
                                                 float* __restrict__ out) {
    __shared__ __align__(16) float  h_s[TJ * HF];        // 4096 f
    __shared__ __align__(16) float  n_s[HH * NS_H];      // 4384 f
    __shared__ __align__(16) float  adj_s[TJ * ADJ_STR]; // 1040 f (transposed [j][ii])
    __shared__ __align__(16) float4 es_s[TJ * HH];       // 64 f4
    __shared__ float zbuf[TI * HH];                      // 256 f

    const int t  = threadIdx.x;
    const int b  = blockIdx.y;
    const int i0 = blockIdx.x * TI;

    // phase-1 identity: thread owns (target row p_ii, head p_h)
    const int p_ii = t >> 2;
    const int p_h  = t & 3;
    const float4 Ed = g_ed[(size_t)(b * NN + i0 + p_ii) * HH + p_h]; // coalesced
    const float dvd = Ed.x, e1d = Ed.y, e2d = Ed.z;
    float z = 0.f;

    // phase-2 identity: thread owns 8 target rows x 8 hf columns
    const int cgrp = t & 31, igrp = t >> 5;
    const int head = cgrp >> 3;
    const int c0   = cgrp << 3;
    float acc[8][8];
#pragma unroll
    for (int r = 0; r < 8; r++)
#pragma unroll
        for (int q = 0; q < 8; q++) acc[r][q] = 0.f;

    const float* nb = n_s + head * NS_H;

    for (int jt = 0; jt < NJT; jt++) {
        const int j0 = jt * TJ;
        __syncthreads();   // previous phase 2 done with n_s / h_s
        // stage h value tile (contiguous 4096 floats)
        {
            const float4* hg  = (const float4*)&g_h[(size_t)(b * NN + j0) * HF];
            float4*       hs4 = (float4*)h_s;
#pragma unroll
            for (int k = 0; k < 4; k++) hs4[t + 256 * k] = hg[t + 256 * k];
        }
        // stage adj tile transposed: adj_s[j][ii] = adj[b][i0+ii][j0+j]
        {
            const int r  = t >> 2;
            const int cc = (t & 3) << 2;
            float4 v = *(const float4*)&adj[(size_t)(b * NN + i0 + r) * NN + j0 + cc];
            adj_s[(cc + 0) * ADJ_STR + r] = v.x;
            adj_s[(cc + 1) * ADJ_STR + r] = v.y;
            adj_s[(cc + 2) * ADJ_STR + r] = v.z;
            adj_s[(cc + 3) * ADJ_STR + r] = v.w;
        }
        if (t < TJ * HH) es_s[t] = g_es[(size_t)(b * NN + j0) * HH + t];
        __syncthreads();
        // phase 1: softmax numerators (no exp — factorized through LeakyReLU)
        {
            float*       np = n_s + p_h * NS_H + p_ii;
            const float* ap = adj_s + p_ii;
#pragma unroll
            for (int j = 0; j < TJ; j++) {
                const float  a = ap[j * ADJ_STR];
                const float4 E = es_s[(j << 2) | p_h];
                float nv = 0.f;
                if (a > 0.5f)
                    nv = (dvd + E.x >= 0.f) ? (e1d * E.y) : (e2d * E.z);
                z += nv;
                np[j * NS_J] = nv;
            }
        }
        __syncthreads();
        // phase 2: outer-product accumulation
#pragma unroll 4
        for (int j = 0; j < TJ; j++) {
            float4 n0  = *(const float4*)&nb[j * NS_J + (igrp << 3)];
            float4 n1  = *(const float4*)&nb[j * NS_J + (igrp << 3) + 4];
            float4 hv0 = *(const float4*)&h_s[(j << 8) + c0];
            float4 hv1 = *(const float4*)&h_s[(j << 8) + c0 + 4];
            float nn[8] = {n0.x, n0.y, n0.z, n0.w, n1.x, n1.y, n1.z, n1.w};
            float hh[8] = {hv0.x, hv0.y, hv0.z, hv0.w, hv1.x, hv1.y, hv1.z, hv1.w};
#pragma unroll
            for (int r = 0; r < 8; r++)
#pragma unroll
                for (int q = 0; q < 8; q++) acc[r][q] += nn[r] * hh[q];
        }
    }
    zbuf[(p_ii << 2) | p_h] = z;
    __syncthreads();
    const float4 b0 = *(const float4*)&bias[c0];
    const float4 b1 = *(const float4*)&bias[c0 + 4];
#pragma unroll
    for (int r = 0; r < 8; r++) {
        const int   ii = (igrp << 3) + r;
        const float rz = 1.f / zbuf[(ii << 2) | head];
        float4 o0 = make_float4(acc[r][0] * rz + b0.x, acc[r][1] * rz + b0.y,
                                acc[r][2] * rz + b0.z, acc[r][3] * rz + b0.w);
        float4 o1 = make_float4(acc[r][4] * rz + b1.x, acc[r][5] * rz + b1.y,
                                acc[r][6] * rz + b1.z, acc[r][7] * rz + b1.w);
        float* op = &out[(size_t)(b * NN + i0 + ii) * HF + c0];
        *(float4*)op       = o0;
        *(float4*)(op + 4) = o1;
    }
}

extern "C" void kernel_launch(void* const* d_in, const int* in_sizes, int n_in,
                              void* d_out, int out_size) {
    const float* x     = (const float*)d_in[0];
    const float* adj   = (const float*)d_in[1];
    const float* Wm    = (const float*)d_in[2];
    const float* a_src = (const float*)d_in[3];
    const float* a_dst = (const float*)d_in[4];
    const float* bias  = (const float*)d_in[5];
    float* out = (float*)d_out;

    k1_gemm<<<dim3(HF / 64, (BB * NN) / 64), 256>>>(x, Wm);
    k2_stats<<<(BB * NN * HH) / 8, 256>>>(a_src, a_dst);
    k3_agg<<<dim3(NN / TI, BB), 256>>>(adj, bias, out);
}

// round 6
// speedup vs baseline: 1.0653x; 1.0653x over previous
#include <cuda_runtime.h>
#include <cstdint>

#define BB 16
#define NN 1024
#define DD 256
#define HH 4
#define FF 64
#define HF 256

#define TI 64
#define TJ 16
#define NJT (NN / TJ)
#define ADJ_STR (TI + 1)           // 65: conflict-decorrelated transpose store
#define NS_J 68                    // ii-stride (TI=64 + 4 pad, keeps 16B align)
#define NS_H (TJ * NS_J + 8)       // 1096: per-head stride, 16B-aligned

typedef unsigned long long u64;

// ---- packed fp32x2 helpers (B300 FFMA2 path; bitwise-exact fp32 halves) ----
__device__ __forceinline__ u64 ffma2(u64 a, u64 b, u64 c) {
    u64 d;
    asm("fma.rn.f32x2 %0, %1, %2, %3;" : "=l"(d) : "l"(a), "l"(b), "l"(c));
    return d;
}
__device__ __forceinline__ u64 pack2(float x) {
    u64 d; unsigned u = __float_as_uint(x);
    asm("mov.b64 %0, {%1, %2};" : "=l"(d) : "r"(u), "r"(u));
    return d;
}
__device__ __forceinline__ float2 unpack2(u64 v) {
    unsigned lo, hi;
    asm("mov.b64 {%0, %1}, %2;" : "=r"(lo), "=r"(hi) : "l"(v));
    return make_float2(__uint_as_float(lo), __uint_as_float(hi));
}

// Scratch (no cudaMalloc allowed)
__device__ float  g_h[BB * NN * HF];                 // 16 MB
__device__ float4 g_es[BB * NN * HH];                // (s, e^s, e^{0.2s}, -)
__device__ float4 g_ed[BB * NN * HH];                // (d, e^d, e^{0.2d}, -)

// ---------------- K1: h[b,n,hf] = sum_d x[b,n,d] * W[d,hf] ----------------
// 64x64 tile, 16 k-slab, 4x4 microtile, FFMA2-packed along rows.
__global__ __launch_bounds__(256) void k1_gemm(const float* __restrict__ X,
                                               const float* __restrict__ Wm) {
    __shared__ float As[16][68];   // transposed A slab, padded (row base 16B aligned)
    __shared__ float Bs[16][64];
    const int t  = threadIdx.x;
    const int m0 = blockIdx.y << 6;
    const int n0 = blockIdx.x << 6;
    const int tx = t & 15, ty = t >> 4;
    u64 acc2[2][4];
#pragma unroll
    for (int p = 0; p < 2; p++)
#pragma unroll
        for (int q = 0; q < 4; q++) acc2[p][q] = 0ull;

    for (int k0 = 0; k0 < DD; k0 += 16) {
        {
            const int arow = t >> 2, ac = (t & 3) << 2;
            float4 av = *(const float4*)&X[(size_t)(m0 + arow) * DD + k0 + ac];
            As[ac + 0][arow] = av.x;
            As[ac + 1][arow] = av.y;
            As[ac + 2][arow] = av.z;
            As[ac + 3][arow] = av.w;
            const int brow = t >> 4, bc = (t & 15) << 2;
            *(float4*)&Bs[brow][bc] =
                *(const float4*)&Wm[(size_t)(k0 + brow) * HF + n0 + bc];
        }
        __syncthreads();
#pragma unroll
        for (int k = 0; k < 16; k++) {
            // a row-pairs: As[k][ty*4..ty*4+4) -> 2 packed pairs (broadcast in warp)
            ulonglong2 a2 = *(const ulonglong2*)&As[k][ty << 2];
            float4 bv = *(const float4*)&Bs[k][tx << 2];
            u64 pb0 = pack2(bv.x), pb1 = pack2(bv.y), pb2 = pack2(bv.z), pb3 = pack2(bv.w);
            acc2[0][0] = ffma2(a2.x, pb0, acc2[0][0]);
            acc2[0][1] = ffma2(a2.x, pb1, acc2[0][1]);
            acc2[0][2] = ffma2(a2.x, pb2, acc2[0][2]);
            acc2[0][3] = ffma2(a2.x, pb3, acc2[0][3]);
            acc2[1][0] = ffma2(a2.y, pb0, acc2[1][0]);
            acc2[1][1] = ffma2(a2.y, pb1, acc2[1][1]);
            acc2[1][2] = ffma2(a2.y, pb2, acc2[1][2]);
            acc2[1][3] = ffma2(a2.y, pb3, acc2[1][3]);
        }
        __syncthreads();
    }
#pragma unroll
    for (int p = 0; p < 2; p++) {
        float2 u0 = unpack2(acc2[p][0]);
        float2 u1 = unpack2(acc2[p][1]);
        float2 u2 = unpack2(acc2[p][2]);
        float2 u3 = unpack2(acc2[p][3]);
        const int r0 = (ty << 2) + (p << 1);
        *(float4*)&g_h[(size_t)(m0 + r0) * HF + n0 + (tx << 2)] =
            make_float4(u0.x, u1.x, u2.x, u3.x);
        *(float4*)&g_h[(size_t)(m0 + r0 + 1) * HF + n0 + (tx << 2)] =
            make_float4(u0.y, u1.y, u2.y, u3.y);
    }
}

// ------- K2: per (b,n,h): s = h . a_src, d = h . a_dst, plus exp packs ------
__global__ __launch_bounds__(256) void k2_stats(const float* __restrict__ a_src,
                                                const float* __restrict__ a_dst) {
    const int gw   = (blockIdx.x * blockDim.x + threadIdx.x) >> 5; // (b*N+n)*H + h
    const int lane = threadIdx.x & 31;
    const int h    = gw & 3;
    const int bn   = gw >> 2;
    const float* hp = &g_h[(size_t)bn * HF + h * FF];
    const float v0 = hp[lane], v1 = hp[lane + 32];
    float s = v0 * a_src[h * FF + lane] + v1 * a_src[h * FF + lane + 32];
    float d = v0 * a_dst[h * FF + lane] + v1 * a_dst[h * FF + lane + 32];
#pragma unroll
    for (int o = 16; o > 0; o >>= 1) {
        s += __shfl_xor_sync(0xffffffffu, s, o);
        d += __shfl_xor_sync(0xffffffffu, d, o);
    }
    if (lane == 0) {
        g_es[gw] = make_float4(s, expf(s), expf(0.2f * s), 0.f);
        g_ed[gw] = make_float4(d, expf(d), expf(0.2f * d), 0.f);
    }
}

// ---- K3: fused masked softmax + aggregation, FFMA2 phase 2 ----
// Phase-2 thread identity: igrp = t>>5 owns rows igrp*8..+8 (as packed pairs),
// lane = t&31 owns cols {lane*4..+4} (head hA=lane>>4) and {128+lane*4..+4}
// (head hB=hA+2). All h_s loads are warp-contiguous (conflict-free); n_s
// row-pairs load as pre-packed ulonglong2 with 2 distinct addrs/warp (bcast).
__global__ __launch_bounds__(256, 2) void k3_agg(const float* __restrict__ adj,
                                                 const float* __restrict__ bias,
                                                 float* __restrict__ out) {
    __shared__ __align__(16) float  h_s[TJ * HF];        // 4096 f
    __shared__ __align__(16) float  n_s[HH * NS_H];      // 4384 f
    __shared__ __align__(16) float  adj_s[TJ * ADJ_STR]; // 1040 f (transposed [j][ii])
    __shared__ __align__(16) float4 es_s[TJ * HH];       // 64 f4
    __shared__ float zbuf[TI * HH];                      // 256 f

    const int t  = threadIdx.x;
    const int b  = blockIdx.y;
    const int i0 = blockIdx.x * TI;

    // phase-1 identity: thread owns (target row p_ii, head p_h)
    const int p_ii = t >> 2;
    const int p_h  = t & 3;
    const float4 Ed = g_ed[(size_t)(b * NN + i0 + p_ii) * HH + p_h];
    const float dvd = Ed.x, e1d = Ed.y, e2d = Ed.z;
    float z = 0.f;

    // phase-2 identity
    const int lane = t & 31, igrp = t >> 5;
    const int hA = lane >> 4;          // head 0 or 1
    const int hB = hA + 2;             // head 2 or 3
    const int cA = lane << 2;          // cols [0,128)
    const int cB = 128 + (lane << 2);  // cols [128,256)
    u64 accA[4][4], accB[4][4];
#pragma unroll
    for (int rp = 0; rp < 4; rp++)
#pragma unroll
        for (int q = 0; q < 4; q++) { accA[rp][q] = 0ull; accB[rp][q] = 0ull; }

    const float* nbA = n_s + hA * NS_H;
    const float* nbB = n_s + hB * NS_H;
    const int    rbase = igrp << 3;

    for (int jt = 0; jt < NJT; jt++) {
        const int j0 = jt * TJ;
        __syncthreads();   // previous phase 2 done with n_s / h_s
        // stage h value tile (contiguous 4096 floats)
        {
            const float4* hg  = (const float4*)&g_h[(size_t)(b * NN + j0) * HF];
            float4*       hs4 = (float4*)h_s;
#pragma unroll
            for (int k = 0; k < 4; k++) hs4[t + 256 * k] = hg[t + 256 * k];
        }
        // stage adj tile transposed: adj_s[j][ii] = adj[b][i0+ii][j0+j]
        {
            const int r  = t >> 2;
            const int cc = (t & 3) << 2;
            float4 v = *(const float4*)&adj[(size_t)(b * NN + i0 + r) * NN + j0 + cc];
            adj_s[(cc + 0) * ADJ_STR + r] = v.x;
            adj_s[(cc + 1) * ADJ_STR + r] = v.y;
            adj_s[(cc + 2) * ADJ_STR + r] = v.z;
            adj_s[(cc + 3) * ADJ_STR + r] = v.w;
        }
        if (t < TJ * HH) es_s[t] = g_es[(size_t)(b * NN + j0) * HH + t];
        __syncthreads();
        // phase 1: softmax numerators (exp factorized through LeakyReLU)
        {
            float*       np = n_s + p_h * NS_H + p_ii;
            const float* ap = adj_s + p_ii;
#pragma unroll
            for (int j = 0; j < TJ; j++) {
                const float  a = ap[j * ADJ_STR];
                const float4 E = es_s[(j << 2) | p_h];
                float nv = 0.f;
                if (a > 0.5f)
                    nv = (dvd + E.x >= 0.f) ? (e1d * E.y) : (e2d * E.z);
                z += nv;
                np[j * NS_J] = nv;
            }
        }
        __syncthreads();
        // phase 2: packed outer-product accumulation
#pragma unroll 2
        for (int j = 0; j < TJ; j++) {
            float4 hvA = *(const float4*)&h_s[(j << 8) + cA];
            float4 hvB = *(const float4*)&h_s[(j << 8) + cB];
            ulonglong2 nA0 = *(const ulonglong2*)&nbA[j * NS_J + rbase];
            ulonglong2 nA1 = *(const ulonglong2*)&nbA[j * NS_J + rbase + 4];
            ulonglong2 nB0 = *(const ulonglong2*)&nbB[j * NS_J + rbase];
            ulonglong2 nB1 = *(const ulonglong2*)&nbB[j * NS_J + rbase + 4];
            u64 pA[4] = {pack2(hvA.x), pack2(hvA.y), pack2(hvA.z), pack2(hvA.w)};
            u64 pB[4] = {pack2(hvB.x), pack2(hvB.y), pack2(hvB.z), pack2(hvB.w)};
            u64 nnA[4] = {nA0.x, nA0.y, nA1.x, nA1.y};
            u64 nnB[4] = {nB0.x, nB0.y, nB1.x, nB1.y};
#pragma unroll
            for (int rp = 0; rp < 4; rp++)
#pragma unroll
                for (int q = 0; q < 4; q++) {
                    accA[rp][q] = ffma2(nnA[rp], pA[q], accA[rp][q]);
                    accB[rp][q] = ffma2(nnB[rp], pB[q], accB[rp][q]);
                }
        }
    }
    zbuf[(p_ii << 2) | p_h] = z;
    __syncthreads();
    const float4 bA = *(const float4*)&bias[cA];
    const float4 bB = *(const float4*)&bias[cB];
#pragma unroll
    for (int rp = 0; rp < 4; rp++) {
        const int r0 = rbase + (rp << 1);
        const float rzA0 = 1.f / zbuf[(r0 << 2) | hA];
        const float rzA1 = 1.f / zbuf[((r0 + 1) << 2) | hA];
        const float rzB0 = 1.f / zbuf[(r0 << 2) | hB];
        const float rzB1 = 1.f / zbuf[((r0 + 1) << 2) | hB];
        float2 uA0 = unpack2(accA[rp][0]), uA1 = unpack2(accA[rp][1]);
        float2 uA2 = unpack2(accA[rp][2]), uA3 = unpack2(accA[rp][3]);
        float2 uB0 = unpack2(accB[rp][0]), uB1 = unpack2(accB[rp][1]);
        float2 uB2 = unpack2(accB[rp][2]), uB3 = unpack2(accB[rp][3]);
        float* op0 = &out[(size_t)(b * NN + i0 + r0) * HF];
        float* op1 = &out[(size_t)(b * NN + i0 + r0 + 1) * HF];
        *(float4*)(op0 + cA) = make_float4(uA0.x * rzA0 + bA.x, uA1.x * rzA0 + bA.y,
                                           uA2.x * rzA0 + bA.z, uA3.x * rzA0 + bA.w);
        *(float4*)(op0 + cB) = make_float4(uB0.x * rzB0 + bB.x, uB1.x * rzB0 + bB.y,
                                           uB2.x * rzB0 + bB.z, uB3.x * rzB0 + bB.w);
        *(float4*)(op1 + cA) = make_float4(uA0.y * rzA1 + bA.x, uA1.y * rzA1 + bA.y,
                                           uA2.y * rzA1 + bA.z, uA3.y * rzA1 + bA.w);
        *(float4*)(op1 + cB) = make_float4(uB0.y * rzB1 + bB.x, uB1.y * rzB1 + bB.y,
                                           uB2.y * rzB1 + bB.z, uB3.y * rzB1 + bB.w);
    }
}

extern "C" void kernel_launch(void* const* d_in, const int* in_sizes, int n_in,
                              void* d_out, int out_size) {
    const float* x     = (const float*)d_in[0];
    const float* adj   = (const float*)d_in[1];
    const float* Wm    = (const float*)d_in[2];
    const float* a_src = (const float*)d_in[3];
    const float* a_dst = (const float*)d_in[4];
    const float* bias  = (const float*)d_in[5];
    float* out = (float*)d_out;

    k1_gemm<<<dim3(HF / 64, (BB * NN) / 64), 256>>>(x, Wm);
    k2_stats<<<(BB * NN * HH) / 8, 256>>>(a_src, a_dst);
    k3_agg<<<dim3(NN / TI, BB), 256>>>(adj, bias, out);
}

// round 8
// speedup vs baseline: 1.1799x; 1.1076x over previous
#include <cuda_runtime.h>
#include <cstdint>

#define BB 16
#define NN 1024
#define DD 256
#define HH 4
#define FF 64
#define HF 256

#define TI 64
#define TJ 16
#define NJT (NN / TJ)
#define ADJ_ROW 20                 // padded row stride (floats): conflict-free 8x4 phase-1 reads
#define NS_J 68                    // ii-stride (TI=64 + 4 pad, keeps 16B align)
#define NS_H (TJ * NS_J + 8)       // 1096: per-head stride, 16B-aligned

typedef unsigned long long u64;

// ---- packed fp32x2 helpers (B300 FFMA2 path; bitwise-exact fp32 halves) ----
__device__ __forceinline__ u64 ffma2(u64 a, u64 b, u64 c) {
    u64 d;
    asm("fma.rn.f32x2 %0, %1, %2, %3;" : "=l"(d) : "l"(a), "l"(b), "l"(c));
    return d;
}
__device__ __forceinline__ u64 pack2(float x) {
    u64 d; unsigned u = __float_as_uint(x);
    asm("mov.b64 %0, {%1, %2};" : "=l"(d) : "r"(u), "r"(u));
    return d;
}
__device__ __forceinline__ float2 unpack2(u64 v) {
    unsigned lo, hi;
    asm("mov.b64 {%0, %1}, %2;" : "=r"(lo), "=r"(hi) : "l"(v));
    return make_float2(__uint_as_float(lo), __uint_as_float(hi));
}
__device__ __forceinline__ uint32_t sptr(const void* p) {
    return (uint32_t)__cvta_generic_to_shared(p);
}
__device__ __forceinline__ void cpa16(uint32_t dst, const void* src) {
    asm volatile("cp.async.cg.shared.global [%0], [%1], 16;" :: "r"(dst), "l"(src));
}
__device__ __forceinline__ void cpa_commit() {
    asm volatile("cp.async.commit_group;" ::: "memory");
}
__device__ __forceinline__ void cpa_wait0() {
    asm volatile("cp.async.wait_group 0;" ::: "memory");
}

// Scratch (no cudaMalloc allowed)
__device__ float  g_h[BB * NN * HF];                 // 16 MB
__device__ float4 g_es[BB * NN * HH];                // (s, e^s, e^{0.2s}, -)
__device__ float4 g_ed[BB * NN * HH];                // (d, e^d, e^{0.2d}, -)

// ---------------- K1: h[b,n,hf] = sum_d x[b,n,d] * W[d,hf] ----------------
// 128x128 block tile, 8-k slab, 8x8 microtile (1 MAC/smem-byte), FFMA2,
// cp.async double-buffered W + reg-prefetch/transpose-STS X, 1 sync per slab.
__global__ __launch_bounds__(256, 2) void k1_gemm(const float* __restrict__ X,
                                                  const float* __restrict__ Wm) {
    __shared__ __align__(16) float As[2][8][132];  // [buf][k][row], 528B/k-row (16B mult)
    __shared__ __align__(16) float Bs[2][8][128];
    const int t  = threadIdx.x;
    const int m0 = blockIdx.y << 7;
    const int n0 = blockIdx.x << 7;
    const int cx = t & 15, ry = t >> 4;       // cols cx*8..+8, rows ry*8..+8

    u64 acc2[4][8];
#pragma unroll
    for (int rp = 0; rp < 4; rp++)
#pragma unroll
        for (int q = 0; q < 8; q++) acc2[rp][q] = 0ull;

    // staging identities
    const int xr = t >> 1, xc = (t & 1) << 2;          // X: 128 rows x 8 k
    const int wk = t >> 5, wc = (t & 31) << 2;         // W: 8 k x 128 cols
    const float* xp = &X[(size_t)(m0 + xr) * DD + xc];

    // prologue: slab 0
    float4 av = *(const float4*)xp;
    cpa16(sptr(&Bs[0][wk][wc]), &Wm[(size_t)wk * HF + n0 + wc]);
    cpa_commit();
    As[0][xc + 0][xr] = av.x;
    As[0][xc + 1][xr] = av.y;
    As[0][xc + 2][xr] = av.z;
    As[0][xc + 3][xr] = av.w;
    cpa_wait0();
    __syncthreads();

    for (int s = 0; s < 32; s++) {
        const int cur = s & 1;
        float4 avn;
        if (s < 31) {
            avn = *(const float4*)(xp + (s + 1) * 8);
            cpa16(sptr(&Bs[cur ^ 1][wk][wc]),
                  &Wm[(size_t)((s + 1) * 8 + wk) * HF + n0 + wc]);
            cpa_commit();
        }
#pragma unroll
        for (int k = 0; k < 8; k++) {
            ulonglong2 a0 = *(const ulonglong2*)&As[cur][k][ry << 3];
            ulonglong2 a1 = *(const ulonglong2*)&As[cur][k][(ry << 3) + 4];
            float4 b0 = *(const float4*)&Bs[cur][k][cx << 3];
            float4 b1 = *(const float4*)&Bs[cur][k][(cx << 3) + 4];
            u64 ar[4] = {a0.x, a0.y, a1.x, a1.y};
            u64 pb[8] = {pack2(b0.x), pack2(b0.y), pack2(b0.z), pack2(b0.w),
                         pack2(b1.x), pack2(b1.y), pack2(b1.z), pack2(b1.w)};
#pragma unroll
            for (int rp = 0; rp < 4; rp++)
#pragma unroll
                for (int q = 0; q < 8; q++)
                    acc2[rp][q] = ffma2(ar[rp], pb[q], acc2[rp][q]);
        }
        if (s < 31) {
            As[cur ^ 1][xc + 0][xr] = avn.x;
            As[cur ^ 1][xc + 1][xr] = avn.y;
            As[cur ^ 1][xc + 2][xr] = avn.z;
            As[cur ^ 1][xc + 3][xr] = avn.w;
        }
        cpa_wait0();
        __syncthreads();
    }
    // epilogue: 8 rows x 8 cols
#pragma unroll
    for (int rp = 0; rp < 4; rp++) {
        float2 u0 = unpack2(acc2[rp][0]), u1 = unpack2(acc2[rp][1]);
        float2 u2 = unpack2(acc2[rp][2]), u3 = unpack2(acc2[rp][3]);
        float2 u4 = unpack2(acc2[rp][4]), u5 = unpack2(acc2[rp][5]);
        float2 u6 = unpack2(acc2[rp][6]), u7 = unpack2(acc2[rp][7]);
        const size_t r0 = (size_t)(m0 + (ry << 3) + (rp << 1));
        float* o0 = &g_h[r0 * HF + n0 + (cx << 3)];
        float* o1 = o0 + HF;
        *(float4*)o0       = make_float4(u0.x, u1.x, u2.x, u3.x);
        *(float4*)(o0 + 4) = make_float4(u4.x, u5.x, u6.x, u7.x);
        *(float4*)o1       = make_float4(u0.y, u1.y, u2.y, u3.y);
        *(float4*)(o1 + 4) = make_float4(u4.y, u5.y, u6.y, u7.y);
    }
}

// ------- K2: per (b,n,h): s = h . a_src, d = h . a_dst, plus exp packs ------
__global__ __launch_bounds__(256) void k2_stats(const float* __restrict__ a_src,
                                                const float* __restrict__ a_dst) {
    const int gw   = (blockIdx.x * blockDim.x + threadIdx.x) >> 5; // (b*N+n)*H + h
    const int lane = threadIdx.x & 31;
    const int h    = gw & 3;
    const int bn   = gw >> 2;
    const float* hp = &g_h[(size_t)bn * HF + h * FF];
    const float v0 = hp[lane], v1 = hp[lane + 32];
    float s = v0 * a_src[h * FF + lane] + v1 * a_src[h * FF + lane + 32];
    float d = v0 * a_dst[h * FF + lane] + v1 * a_dst[h * FF + lane + 32];
#pragma unroll
    for (int o = 16; o > 0; o >>= 1) {
        s += __shfl_xor_sync(0xffffffffu, s, o);
        d += __shfl_xor_sync(0xffffffffu, d, o);
    }
    if (lane == 0) {
        g_es[gw] = make_float4(s, expf(s), expf(0.2f * s), 0.f);
        g_ed[gw] = make_float4(d, expf(d), expf(0.2f * d), 0.f);
    }
}

// ---- K3: fused masked softmax + aggregation, FFMA2 + cp.async pipeline ----
// Dynamic smem layout (bytes):
#define K3_H_OFF   0
#define K3_H_BUF   16384
#define K3_N_OFF   32768
#define K3_ADJ_OFF 50304
#define K3_ADJ_BUF 5120
#define K3_ES_OFF  60544
#define K3_ES_BUF  1024
#define K3_Z_OFF   62592
#define K3_SMEM    63616

__global__ __launch_bounds__(256, 2) void k3_agg(const float* __restrict__ adj,
                                                 const float* __restrict__ bias,
                                                 float* __restrict__ out) {
    extern __shared__ __align__(16) char smem3[];
    float* hS   = (float*)(smem3 + K3_H_OFF);
    float* nS   = (float*)(smem3 + K3_N_OFF);
    float* adjS = (float*)(smem3 + K3_ADJ_OFF);
    float* esS  = (float*)(smem3 + K3_ES_OFF);
    float* zS   = (float*)(smem3 + K3_Z_OFF);

    const int t  = threadIdx.x;
    const int b  = blockIdx.y;
    const int i0 = blockIdx.x * TI;

    // phase-1 identity: thread owns (target row p_ii, head p_h)
    const int p_ii = t >> 2;
    const int p_h  = t & 3;
    const float4 Ed = g_ed[(size_t)(b * NN + i0 + p_ii) * HH + p_h];
    const float dvd = Ed.x, e1d = Ed.y, e2d = Ed.z;
    float z = 0.f;

    // phase-2 identity
    const int lane = t & 31, igrp = t >> 5;
    const int hA = lane >> 4;          // head 0 or 1
    const int hB = hA + 2;             // head 2 or 3
    const int cA = lane << 2;          // cols [0,128)
    const int cB = 128 + (lane << 2);  // cols [128,256)
    u64 accA[4][4], accB[4][4];
#pragma unroll
    for (int rp = 0; rp < 4; rp++)
#pragma unroll
        for (int q = 0; q < 4; q++) { accA[rp][q] = 0ull; accB[rp][q] = 0ull; }

    const float* nbA = nS + hA * NS_H;
    const float* nbB = nS + hB * NS_H;
    const int    rbase = igrp << 3;

    // staging identities
    const int ar_r = t >> 2, ar_c = (t & 3) << 2;   // adj: 64 rows x 16 cols

    // prologue: stage tile 0 into buf 0
    {
        const float* hg = &g_h[(size_t)(b * NN) * HF];
#pragma unroll
        for (int k = 0; k < 4; k++)
            cpa16(sptr(hS + ((t + (k << 8)) << 2)), hg + ((t + (k << 8)) << 2));
        cpa16(sptr(adjS + ar_r * ADJ_ROW + ar_c),
              &adj[(size_t)(b * NN + i0 + ar_r) * NN + ar_c]);
        if (t < TJ * HH)
            cpa16(sptr(esS + (t << 2)), &g_es[(size_t)(b * NN) * HH + t]);
        cpa_commit();
    }

    for (int jt = 0; jt < NJT; jt++) {
        const int cur = jt & 1;
        cpa_wait0();
        __syncthreads();   // tile jt staged & visible; n_s free (phase2 jt-1 done)

        // phase 1: softmax numerators (exp factorized through LeakyReLU)
        {
            const float* ap  = adjS + cur * (K3_ADJ_BUF / 4) + p_ii * ADJ_ROW;
            const float4* ep = (const float4*)(esS + cur * (K3_ES_BUF / 4));
            float* np = nS + p_h * NS_H + p_ii;
#pragma unroll
            for (int j = 0; j < TJ; j++) {
                const float  a = ap[j];
                const float4 E = ep[(j << 2) | p_h];
                float nv = 0.f;
                if (a > 0.5f)
                    nv = (dvd + E.x >= 0.f) ? (e1d * E.y) : (e2d * E.z);
                z += nv;
                np[j * NS_J] = nv;
            }
        }
        // issue staging for tile jt+1 into the other buffer (overlaps phase 2)
        if (jt + 1 < NJT) {
            const int   nb = cur ^ 1;
            const int   j1 = (jt + 1) * TJ;
            const float* hg = &g_h[(size_t)(b * NN + j1) * HF];
            float* hd = hS + nb * (K3_H_BUF / 4);
#pragma unroll
            for (int k = 0; k < 4; k++)
                cpa16(sptr(hd + ((t + (k << 8)) << 2)), hg + ((t + (k << 8)) << 2));
            cpa16(sptr(adjS + nb * (K3_ADJ_BUF / 4) + ar_r * ADJ_ROW + ar_c),
                  &adj[(size_t)(b * NN + i0 + ar_r) * NN + j1 + ar_c]);
            if (t < TJ * HH)
                cpa16(sptr(esS + nb * (K3_ES_BUF / 4) + (t << 2)),
                      &g_es[(size_t)(b * NN + j1) * HH + t]);
        }
        cpa_commit();
        __syncthreads();   // n_s visible to phase 2

        // phase 2: packed outer-product accumulation
        const float* hb = hS + cur * (K3_H_BUF / 4);
#pragma unroll 2
        for (int j = 0; j < TJ; j++) {
            float4 hvA = *(const float4*)&hb[(j << 8) + cA];
            float4 hvB = *(const float4*)&hb[(j << 8) + cB];
            ulonglong2 nA0 = *(const ulonglong2*)&nbA[j * NS_J + rbase];
            ulonglong2 nA1 = *(const ulonglong2*)&nbA[j * NS_J + rbase + 4];
            ulonglong2 nB0 = *(const ulonglong2*)&nbB[j * NS_J + rbase];
            ulonglong2 nB1 = *(const ulonglong2*)&nbB[j * NS_J + rbase + 4];
            u64 pA[4] = {pack2(hvA.x), pack2(hvA.y), pack2(hvA.z), pack2(hvA.w)};
            u64 pB[4] = {pack2(hvB.x), pack2(hvB.y), pack2(hvB.z), pack2(hvB.w)};
            u64 nnA[4] = {nA0.x, nA0.y, nA1.x, nA1.y};
            u64 nnB[4] = {nB0.x, nB0.y, nB1.x, nB1.y};
#pragma unroll
            for (int rp = 0; rp < 4; rp++)
#pragma unroll
                for (int q = 0; q < 4; q++) {
                    accA[rp][q] = ffma2(nnA[rp], pA[q], accA[rp][q]);
                    accB[rp][q] = ffma2(nnB[rp], pB[q], accB[rp][q]);
                }
        }
    }
    zS[(p_ii << 2) | p_h] = z;
    __syncthreads();
    const float4 bA = *(const float4*)&bias[cA];
    const float4 bB = *(const float4*)&bias[cB];
#pragma unroll
    for (int rp = 0; rp < 4; rp++) {
        const int r0 = rbase + (rp << 1);
        const float rzA0 = 1.f / zS[(r0 << 2) | hA];
        const float rzA1 = 1.f / zS[((r0 + 1) << 2) | hA];
        const float rzB0 = 1.f / zS[(r0 << 2) | hB];
        const float rzB1 = 1.f / zS[((r0 + 1) << 2) | hB];
        float2 uA0 = unpack2(accA[rp][0]), uA1 = unpack2(accA[rp][1]);
        float2 uA2 = unpack2(accA[rp][2]), uA3 = unpack2(accA[rp][3]);
        float2 uB0 = unpack2(accB[rp][0]), uB1 = unpack2(accB[rp][1]);
        float2 uB2 = unpack2(accB[rp][2]), uB3 = unpack2(accB[rp][3]);
        float* op0 = &out[(size_t)(b * NN + i0 + r0) * HF];
        float* op1 = op0 + HF;
        *(float4*)(op0 + cA) = make_float4(uA0.x * rzA0 + bA.x, uA1.x * rzA0 + bA.y,
                                           uA2.x * rzA0 + bA.z, uA3.x * rzA0 + bA.w);
        *(float4*)(op0 + cB) = make_float4(uB0.x * rzB0 + bB.x, uB1.x * rzB0 + bB.y,
                                           uB2.x * rzB0 + bB.z, uB3.x * rzB0 + bB.w);
        *(float4*)(op1 + cA) = make_float4(uA0.y * rzA1 + bA.x, uA1.y * rzA1 + bA.y,
                                           uA2.y * rzA1 + bA.z, uA3.y * rzA1 + bA.w);
        *(float4*)(op1 + cB) = make_float4(uB0.y * rzB1 + bB.x, uB1.y * rzB1 + bB.y,
                                           uB2.y * rzB1 + bB.z, uB3.y * rzB1 + bB.w);
    }
}

extern "C" void kernel_launch(void* const* d_in, const int* in_sizes, int n_in,
                              void* d_out, int out_size) {
    const float* x     = (const float*)d_in[0];
    const float* adj   = (const float*)d_in[1];
    const float* Wm    = (const float*)d_in[2];
    const float* a_src = (const float*)d_in[3];
    const float* a_dst = (const float*)d_in[4];
    const float* bias  = (const float*)d_in[5];
    float* out = (float*)d_out;

    cudaFuncSetAttribute(k3_agg, cudaFuncAttributeMaxDynamicSharedMemorySize, K3_SMEM);

    k1_gemm<<<dim3(HF / 128, (BB * NN) / 128), 256>>>(x, Wm);
    k2_stats<<<(BB * NN * HH) / 8, 256>>>(a_src, a_dst);
    k3_agg<<<dim3(NN / TI, BB), 256, K3_SMEM>>>(adj, bias, out);
}

// round 16
// speedup vs baseline: 1.2899x; 1.0932x over previous
#include <cuda_runtime.h>
#include <cuda_bf16.h>
#include <mma.h>
#include <cstdint>

using namespace nvcuda;

#define BB 16
#define NN 1024
#define DD 256
#define HH 4
#define FF 64
#define HF 256

#define TI 64
#define TJ 16
#define NJT (NN / TJ)
#define ADJ_ROW 20

typedef unsigned long long u64;

__device__ __forceinline__ uint32_t sptr(const void* p) {
    return (uint32_t)__cvta_generic_to_shared(p);
}
__device__ __forceinline__ void cpa16(uint32_t dst, const void* src) {
    asm volatile("cp.async.cg.shared.global [%0], [%1], 16;" :: "r"(dst), "l"(src));
}
__device__ __forceinline__ void cpa_commit() {
    asm volatile("cp.async.commit_group;" ::: "memory");
}
__device__ __forceinline__ void cpa_wait0() {
    asm volatile("cp.async.wait_group 0;" ::: "memory");
}

// Scratch (no cudaMalloc allowed)
__device__ float         g_h[BB * NN * HF];       // 16 MB fp32
__device__ float4        g_es[BB * NN * HH];      // (s, e^s, e^{0.2s}, -)
__device__ float4        g_ed[BB * NN * HH];
__device__ __nv_bfloat16 g_xhi[BB * NN * DD];
__device__ __nv_bfloat16 g_xlo[BB * NN * DD];
__device__ __nv_bfloat16 g_whiT[HF * DD];         // W^T split (row = hf, col = d)
__device__ __nv_bfloat16 g_wloT[HF * DD];
__device__ __nv_bfloat16 g_hhi[BB * NN * HF];     // h split for k3 B operand
__device__ __nv_bfloat16 g_hlo[BB * NN * HF];

// -------- K0a: split x into bf16 hi/lo pairs (error-compensated) --------
__global__ __launch_bounds__(256) void k0_split_x(const float* __restrict__ X) {
    const int i = blockIdx.x * 256 + threadIdx.x;       // over 1M float4
    float4 v = ((const float4*)X)[i];
    __nv_bfloat16 h0 = __float2bfloat16(v.x), h1 = __float2bfloat16(v.y);
    __nv_bfloat16 h2 = __float2bfloat16(v.z), h3 = __float2bfloat16(v.w);
    __nv_bfloat16 l0 = __float2bfloat16(v.x - __bfloat162float(h0));
    __nv_bfloat16 l1 = __float2bfloat16(v.y - __bfloat162float(h1));
    __nv_bfloat16 l2 = __float2bfloat16(v.z - __bfloat162float(h2));
    __nv_bfloat16 l3 = __float2bfloat16(v.w - __bfloat162float(h3));
    __nv_bfloat162 ph0; ph0.x = h0; ph0.y = h1;
    __nv_bfloat162 ph1; ph1.x = h2; ph1.y = h3;
    __nv_bfloat162 pl0; pl0.x = l0; pl0.y = l1;
    __nv_bfloat162 pl1; pl1.x = l2; pl1.y = l3;
    ((__nv_bfloat162*)g_xhi)[2 * i]     = ph0;
    ((__nv_bfloat162*)g_xhi)[2 * i + 1] = ph1;
    ((__nv_bfloat162*)g_xlo)[2 * i]     = pl0;
    ((__nv_bfloat162*)g_xlo)[2 * i + 1] = pl1;
}

// -------- K0b: transpose + split W --------
__global__ __launch_bounds__(256) void k0_split_w(const float* __restrict__ Wm) {
    const int idx = blockIdx.x * 256 + threadIdx.x;     // over 65536
    const float v = Wm[idx];
    const int d = idx >> 8, n = idx & 255;
    __nv_bfloat16 hi = __float2bfloat16(v);
    __nv_bfloat16 lo = __float2bfloat16(v - __bfloat162float(hi));
    g_whiT[n * DD + d] = hi;
    g_wloT[n * DD + d] = lo;
}

// -------- K1: h = x@W via wmma bf16 3-term split --------
// CTA 128x128 tile; 8 warps as 4(m)x2(n); K in 4 slabs of 64.
// smem rows padded to 72 bf16 (144B) -> conflict-decorrelated ldmatrix.
#define K1_LDA 72
#define K1_AHI 0
#define K1_ALO 9216
#define K1_BHI 18432
#define K1_BLO 27648
#define K1_SMEM 73728

__global__ __launch_bounds__(256) void k1_mma() {
    extern __shared__ __align__(16) __nv_bfloat16 smA[];
    const int t  = threadIdx.x;
    const int w  = t >> 5;
    const int wm = w & 3;          // 32-row block
    const int wn = w >> 2;         // 64-col block
    const int n0 = blockIdx.x << 7;
    const int m0 = blockIdx.y << 7;

    wmma::fragment<wmma::accumulator, 16, 16, 16, float> acc[2][4];
#pragma unroll
    for (int im = 0; im < 2; im++)
#pragma unroll
        for (int fn = 0; fn < 4; fn++) wmma::fill_fragment(acc[im][fn], 0.f);

    for (int s = 0; s < 4; s++) {
        const int k0 = s << 6;
        // stage 4 operands: 128 rows x 64 bf16 each (8x16B chunks per row)
#pragma unroll
        for (int q = 0; q < 4; q++) {
            const int idx = (q << 8) + t;          // 0..1023
            const int row = idx >> 3, ch = idx & 7;
            const uint32_t doff = (row * K1_LDA + ch * 8) * 2;
            const size_t asrc = (size_t)(m0 + row) * DD + k0 + ch * 8;
            const size_t bsrc = (size_t)(n0 + row) * DD + k0 + ch * 8;
            cpa16(sptr(smA) + K1_AHI * 2 + doff, g_xhi + asrc);
            cpa16(sptr(smA) + K1_ALO * 2 + doff, g_xlo + asrc);
            cpa16(sptr(smA) + K1_BHI * 2 + doff, g_whiT + bsrc);
            cpa16(sptr(smA) + K1_BLO * 2 + doff, g_wloT + bsrc);
        }
        cpa_commit();
        cpa_wait0();
        __syncthreads();

#pragma unroll
        for (int kst = 0; kst < 4; kst++) {
            wmma::fragment<wmma::matrix_a, 16, 16, 16, __nv_bfloat16, wmma::row_major> ahi[2], alo[2];
#pragma unroll
            for (int im = 0; im < 2; im++) {
                const int aoff = (wm * 32 + im * 16) * K1_LDA + kst * 16;
                wmma::load_matrix_sync(ahi[im], smA + K1_AHI + aoff, K1_LDA);
                wmma::load_matrix_sync(alo[im], smA + K1_ALO + aoff, K1_LDA);
            }
#pragma unroll
            for (int fn = 0; fn < 4; fn++) {
                wmma::fragment<wmma::matrix_b, 16, 16, 16, __nv_bfloat16, wmma::col_major> bhi, blo;
                const int boff = (wn * 64 + fn * 16) * K1_LDA + kst * 16;
                wmma::load_matrix_sync(bhi, smA + K1_BHI + boff, K1_LDA);
                wmma::load_matrix_sync(blo, smA + K1_BLO + boff, K1_LDA);
#pragma unroll
                for (int im = 0; im < 2; im++) {
                    wmma::mma_sync(acc[im][fn], ahi[im], bhi, acc[im][fn]);
                    wmma::mma_sync(acc[im][fn], ahi[im], blo, acc[im][fn]);
                    wmma::mma_sync(acc[im][fn], alo[im], bhi, acc[im][fn]);
                }
            }
        }
        __syncthreads();   // all reads done before restaging
    }
#pragma unroll
    for (int im = 0; im < 2; im++)
#pragma unroll
        for (int fn = 0; fn < 4; fn++)
            wmma::store_matrix_sync(
                &g_h[(size_t)(m0 + wm * 32 + im * 16) * HF + n0 + wn * 64 + fn * 16],
                acc[im][fn], HF, wmma::mem_row_major);
}

// ------- K2: per (b,n,h) logit stats + exp packs + bf16 h split -------
__global__ __launch_bounds__(256) void k2_stats(const float* __restrict__ a_src,
                                                const float* __restrict__ a_dst) {
    const int gw   = (blockIdx.x * blockDim.x + threadIdx.x) >> 5;
    const int lane = threadIdx.x & 31;
    const int h    = gw & 3;
    const int bn   = gw >> 2;
    const float* hp = &g_h[(size_t)bn * HF + h * FF];
    const float v0 = hp[lane], v1 = hp[lane + 32];
    // bf16 split of h for k3's B operand
    {
        const size_t o = (size_t)bn * HF + h * FF + lane;
        __nv_bfloat16 b0 = __float2bfloat16(v0);
        __nv_bfloat16 b1 = __float2bfloat16(v1);
        g_hhi[o]      = b0;
        g_hhi[o + 32] = b1;
        g_hlo[o]      = __float2bfloat16(v0 - __bfloat162float(b0));
        g_hlo[o + 32] = __float2bfloat16(v1 - __bfloat162float(b1));
    }
    float s = v0 * a_src[h * FF + lane] + v1 * a_src[h * FF + lane + 32];
    float d = v0 * a_dst[h * FF + lane] + v1 * a_dst[h * FF + lane + 32];
#pragma unroll
    for (int o = 16; o > 0; o >>= 1) {
        s += __shfl_xor_sync(0xffffffffu, s, o);
        d += __shfl_xor_sync(0xffffffffu, d, o);
    }
    if (lane == 0) {
        g_es[gw] = make_float4(s, expf(s), expf(0.2f * s), 0.f);
        g_ed[gw] = make_float4(d, expf(d), expf(0.2f * d), 0.f);
    }
}

// ---- K3: fused masked softmax + aggregation, wmma phase 2 ----
// Phase 1 (scalar fp32): numerators + exact Z, emits bf16 hi/lo A-matrix.
// Phase 2 (wmma): warp w = (head = w>>1, ihalf = w&1) accumulates
//   acc[32 x 64] += n[32 x 16] @ h[16 x 64]   (3-term split)
// smem layout (bytes):
#define K3_HHI_OFF 0                 // 2 x 16x264 bf16 = 16896
#define K3_HLO_OFF 16896
#define K3_ADJ_OFF 33792             // 2 x 64x20 f32 = 10240
#define K3_ES_OFF  44032             // 2 x 64 float4 = 2048
#define K3_NHI_OFF 46080             // 4 x 64x24 bf16 = 12288
#define K3_NLO_OFF 58368
#define K3_Z_OFF   70656             // 256 f32
#define K3_SCR_OFF 71680             // 8 x 16x20 f32 = 10240
#define K3_SMEM    81920
#define H_LD 264                     // 16B-multiple, conflict-decorrelated
#define N_LD 24
#define HBUF 4224                    // elems per h buffer (16*264)

__global__ __launch_bounds__(256) void k3_agg(const float* __restrict__ adj,
                                              const float* __restrict__ bias,
                                              float* __restrict__ out) {
    extern __shared__ __align__(16) char sm3[];
    __nv_bfloat16* hHi = (__nv_bfloat16*)(sm3 + K3_HHI_OFF);
    __nv_bfloat16* hLo = (__nv_bfloat16*)(sm3 + K3_HLO_OFF);
    float*         adjS = (float*)(sm3 + K3_ADJ_OFF);
    float*         esS  = (float*)(sm3 + K3_ES_OFF);
    __nv_bfloat16* nHi = (__nv_bfloat16*)(sm3 + K3_NHI_OFF);
    __nv_bfloat16* nLo = (__nv_bfloat16*)(sm3 + K3_NLO_OFF);
    float*         zS   = (float*)(sm3 + K3_Z_OFF);
    float*         scrF = (float*)(sm3 + K3_SCR_OFF);

    const int t  = threadIdx.x;
    const int b  = blockIdx.y;
    const int i0 = blockIdx.x * TI;

    // phase-1 identity
    const int p_ii = t >> 2;
    const int p_h  = t & 3;
    const float4 Ed = g_ed[(size_t)(b * NN + i0 + p_ii) * HH + p_h];
    const float dvd = Ed.x, e1d = Ed.y, e2d = Ed.z;
    float z = 0.f;

    // phase-2 identity
    const int w     = t >> 5;
    const int lane  = t & 31;
    const int head  = w >> 1;
    const int ihalf = w & 1;
    wmma::fragment<wmma::accumulator, 16, 16, 16, float> acc[2][4];
#pragma unroll
    for (int im = 0; im < 2; im++)
#pragma unroll
        for (int fn = 0; fn < 4; fn++) wmma::fill_fragment(acc[im][fn], 0.f);

    const int ar_r = t >> 2, ar_c = (t & 3) << 2;

    // stage tile jt into buffer bf (h bf16 hi/lo + adj + es)
    auto stage = [&](int jt, int bf) {
        const int j0 = jt * TJ;
        const size_t hb = (size_t)(b * NN + j0) * HF;
#pragma unroll
        for (int q = 0; q < 2; q++) {
            const int idx = (q << 8) + t;            // 0..511 per array
            const int row = idx >> 5, ch = idx & 31; // 16 rows x 32 chunks
            const uint32_t doff = (bf * HBUF + row * H_LD + ch * 8) * 2;
            cpa16(sptr(hHi) + doff, g_hhi + hb + row * HF + ch * 8);
            cpa16(sptr(hLo) + doff, g_hlo + hb + row * HF + ch * 8);
        }
        cpa16(sptr(adjS + bf * (64 * ADJ_ROW) + ar_r * ADJ_ROW + ar_c),
              &adj[(size_t)(b * NN + i0 + ar_r) * NN + j0 + ar_c]);
        if (t < TJ * HH)
            cpa16(sptr(esS + bf * 256 + (t << 2)),
                  &g_es[(size_t)(b * NN + j0) * HH + t]);
    };

    stage(0, 0);
    cpa_commit();

    for (int jt = 0; jt < NJT; jt++) {
        const int cur = jt & 1;
        cpa_wait0();
        __syncthreads();   // tile jt visible; nS free (all warps done phase 2 jt-1)

        // issue staging for jt+1 (overlaps phase 1 AND phase 2)
        if (jt + 1 < NJT) stage(jt + 1, cur ^ 1);
        cpa_commit();

        // phase 1: numerators (exp factorized through LeakyReLU), exact fp32 Z
        {
            const float*  ap = adjS + cur * (64 * ADJ_ROW) + p_ii * ADJ_ROW;
            const float4* ep = (const float4*)(esS + cur * 256);
            __nv_bfloat16* nhp = nHi + p_h * (64 * N_LD) + p_ii * N_LD;
            __nv_bfloat16* nlp = nLo + p_h * (64 * N_LD) + p_ii * N_LD;
#pragma unroll
            for (int j = 0; j < TJ; j++) {
                const float  a = ap[j];
                const float4 E = ep[(j << 2) | p_h];
                float nv = 0.f;
                if (a > 0.5f)
                    nv = (dvd + E.x >= 0.f) ? (e1d * E.y) : (e2d * E.z);
                z += nv;
                __nv_bfloat16 hi = __float2bfloat16(nv);
                nhp[j] = hi;
                nlp[j] = __float2bfloat16(nv - __bfloat162float(hi));
            }
        }
        __syncthreads();   // n tiles visible to consumer warps

        // phase 2: wmma accumulation
        {
            wmma::fragment<wmma::matrix_a, 16, 16, 16, __nv_bfloat16, wmma::row_major> ahi[2], alo[2];
#pragma unroll
            for (int im = 0; im < 2; im++) {
                const int aoff = head * (64 * N_LD) + (ihalf * 32 + im * 16) * N_LD;
                wmma::load_matrix_sync(ahi[im], nHi + aoff, N_LD);
                wmma::load_matrix_sync(alo[im], nLo + aoff, N_LD);
            }
            const __nv_bfloat16* hHb = hHi + cur * HBUF;
            const __nv_bfloat16* hLb = hLo + cur * HBUF;
#pragma unroll
            for (int fn = 0; fn < 4; fn++) {
                wmma::fragment<wmma::matrix_b, 16, 16, 16, __nv_bfloat16, wmma::row_major> bhi, blo;
                const int boff = head * 64 + fn * 16;
                wmma::load_matrix_sync(bhi, hHb + boff, H_LD);
                wmma::load_matrix_sync(blo, hLb + boff, H_LD);
#pragma unroll
                for (int im = 0; im < 2; im++) {
                    wmma::mma_sync(acc[im][fn], ahi[im], bhi, acc[im][fn]);
                    wmma::mma_sync(acc[im][fn], ahi[im], blo, acc[im][fn]);
                    wmma::mma_sync(acc[im][fn], alo[im], bhi, acc[im][fn]);
                }
            }
        }
    }

    zS[(p_ii << 2) | p_h] = z;
    __syncthreads();

    // epilogue: frag -> per-warp scratch -> /Z + bias -> gmem
    float* scr = scrF + w * (16 * 20);
#pragma unroll
    for (int im = 0; im < 2; im++) {
#pragma unroll
        for (int fn = 0; fn < 4; fn++) {
            wmma::store_matrix_sync(scr, acc[im][fn], 20, wmma::mem_row_major);
            __syncwarp();
#pragma unroll
            for (int e = 0; e < 8; e++) {
                const int idx = lane + (e << 5);
                const int row = idx >> 4, col = idx & 15;
                const int ii  = ihalf * 32 + im * 16 + row;
                const int c   = head * 64 + fn * 16 + col;
                const float rz = 1.f / zS[(ii << 2) | head];
                out[(size_t)(b * NN + i0 + ii) * HF + c] =
                    scr[row * 20 + col] * rz + bias[c];
            }
            __syncwarp();
        }
    }
}

extern "C" void kernel_launch(void* const* d_in, const int* in_sizes, int n_in,
                              void* d_out, int out_size) {
    const float* x     = (const float*)d_in[0];
    const float* adj   = (const float*)d_in[1];
    const float* Wm    = (const float*)d_in[2];
    const float* a_src = (const float*)d_in[3];
    const float* a_dst = (const float*)d_in[4];
    const float* bias  = (const float*)d_in[5];
    float* out = (float*)d_out;

    cudaFuncSetAttribute(k1_mma, cudaFuncAttributeMaxDynamicSharedMemorySize, K1_SMEM);
    cudaFuncSetAttribute(k3_agg, cudaFuncAttributeMaxDynamicSharedMemorySize, K3_SMEM);

    k0_split_x<<<(BB * NN * DD) / 4 / 256, 256>>>(x);
    k0_split_w<<<(DD * HF) / 256, 256>>>(Wm);
    k1_mma<<<dim3(HF / 128, (BB * NN) / 128), 256, K1_SMEM>>>();
    k2_stats<<<(BB * NN * HH) / 8, 256>>>(a_src, a_dst);
    k3_agg<<<dim3(NN / TI, BB), 256, K3_SMEM>>>(adj, bias, out);
}

// round 17
// speedup vs baseline: 2.2171x; 1.7189x over previous
#include <cuda_runtime.h>
#include <cuda_bf16.h>
#include <cuda_fp16.h>
#include <mma.h>
#include <cstdint>

using namespace nvcuda;

#define BB 16
#define NN 1024
#define DD 256
#define HH 4
#define FF 64
#define HF 256

#define TI 64
#define TJ 32
#define NJT (NN / TJ)
#define ADJ_ROW 36                 // 32 + 4 pad floats (144B rows)

typedef unsigned long long u64;

__device__ __forceinline__ uint32_t sptr(const void* p) {
    return (uint32_t)__cvta_generic_to_shared(p);
}
__device__ __forceinline__ void cpa16(uint32_t dst, const void* src) {
    asm volatile("cp.async.cg.shared.global [%0], [%1], 16;" :: "r"(dst), "l"(src));
}
__device__ __forceinline__ void cpa_commit() {
    asm volatile("cp.async.commit_group;" ::: "memory");
}
__device__ __forceinline__ void cpa_wait0() {
    asm volatile("cp.async.wait_group 0;" ::: "memory");
}

// Scratch (no cudaMalloc allowed)
__device__ float         g_h[BB * NN * HF];       // 16 MB fp32
__device__ float4        g_es[BB * NN * HH];      // (s, e^s, e^{0.2s}, -)
__device__ float4        g_ed[BB * NN * HH];      // (d, e^{d-c}, e^{0.2d-c}, -)
__device__ __nv_bfloat16 g_xhi[BB * NN * DD];
__device__ __nv_bfloat16 g_xlo[BB * NN * DD];
__device__ __nv_bfloat16 g_whiT[HF * DD];
__device__ __nv_bfloat16 g_wloT[HF * DD];
__device__ __half        g_hf16[BB * NN * HF];    // h in fp16 for k3 B operand

// -------- K0a: split x into bf16 hi/lo pairs (error-compensated) --------
__global__ __launch_bounds__(256) void k0_split_x(const float* __restrict__ X) {
    const int i = blockIdx.x * 256 + threadIdx.x;
    float4 v = ((const float4*)X)[i];
    __nv_bfloat16 h0 = __float2bfloat16(v.x), h1 = __float2bfloat16(v.y);
    __nv_bfloat16 h2 = __float2bfloat16(v.z), h3 = __float2bfloat16(v.w);
    __nv_bfloat16 l0 = __float2bfloat16(v.x - __bfloat162float(h0));
    __nv_bfloat16 l1 = __float2bfloat16(v.y - __bfloat162float(h1));
    __nv_bfloat16 l2 = __float2bfloat16(v.z - __bfloat162float(h2));
    __nv_bfloat16 l3 = __float2bfloat16(v.w - __bfloat162float(h3));
    __nv_bfloat162 ph0; ph0.x = h0; ph0.y = h1;
    __nv_bfloat162 ph1; ph1.x = h2; ph1.y = h3;
    __nv_bfloat162 pl0; pl0.x = l0; pl0.y = l1;
    __nv_bfloat162 pl1; pl1.x = l2; pl1.y = l3;
    ((__nv_bfloat162*)g_xhi)[2 * i]     = ph0;
    ((__nv_bfloat162*)g_xhi)[2 * i + 1] = ph1;
    ((__nv_bfloat162*)g_xlo)[2 * i]     = pl0;
    ((__nv_bfloat162*)g_xlo)[2 * i + 1] = pl1;
}

// -------- K0b: transpose + split W --------
__global__ __launch_bounds__(256) void k0_split_w(const float* __restrict__ Wm) {
    const int idx = blockIdx.x * 256 + threadIdx.x;
    const float v = Wm[idx];
    const int d = idx >> 8, n = idx & 255;
    __nv_bfloat16 hi = __float2bfloat16(v);
    __nv_bfloat16 lo = __float2bfloat16(v - __bfloat162float(hi));
    g_whiT[n * DD + d] = hi;
    g_wloT[n * DD + d] = lo;
}

// -------- K1: h = x@W via wmma bf16 3-term split (unchanged) --------
#define K1_LDA 72
#define K1_AHI 0
#define K1_ALO 9216
#define K1_BHI 18432
#define K1_BLO 27648
#define K1_SMEM 73728

__global__ __launch_bounds__(256) void k1_mma() {
    extern __shared__ __align__(16) __nv_bfloat16 smA[];
    const int t  = threadIdx.x;
    const int w  = t >> 5;
    const int wm = w & 3;
    const int wn = w >> 2;
    const int n0 = blockIdx.x << 7;
    const int m0 = blockIdx.y << 7;

    wmma::fragment<wmma::accumulator, 16, 16, 16, float> acc[2][4];
#pragma unroll
    for (int im = 0; im < 2; im++)
#pragma unroll
        for (int fn = 0; fn < 4; fn++) wmma::fill_fragment(acc[im][fn], 0.f);

    for (int s = 0; s < 4; s++) {
        const int k0 = s << 6;
#pragma unroll
        for (int q = 0; q < 4; q++) {
            const int idx = (q << 8) + t;
            const int row = idx >> 3, ch = idx & 7;
            const uint32_t doff = (row * K1_LDA + ch * 8) * 2;
            const size_t asrc = (size_t)(m0 + row) * DD + k0 + ch * 8;
            const size_t bsrc = (size_t)(n0 + row) * DD + k0 + ch * 8;
            cpa16(sptr(smA) + K1_AHI * 2 + doff, g_xhi + asrc);
            cpa16(sptr(smA) + K1_ALO * 2 + doff, g_xlo + asrc);
            cpa16(sptr(smA) + K1_BHI * 2 + doff, g_whiT + bsrc);
            cpa16(sptr(smA) + K1_BLO * 2 + doff, g_wloT + bsrc);
        }
        cpa_commit();
        cpa_wait0();
        __syncthreads();

#pragma unroll
        for (int kst = 0; kst < 4; kst++) {
            wmma::fragment<wmma::matrix_a, 16, 16, 16, __nv_bfloat16, wmma::row_major> ahi[2], alo[2];
#pragma unroll
            for (int im = 0; im < 2; im++) {
                const int aoff = (wm * 32 + im * 16) * K1_LDA + kst * 16;
                wmma::load_matrix_sync(ahi[im], smA + K1_AHI + aoff, K1_LDA);
                wmma::load_matrix_sync(alo[im], smA + K1_ALO + aoff, K1_LDA);
            }
#pragma unroll
            for (int fn = 0; fn < 4; fn++) {
                wmma::fragment<wmma::matrix_b, 16, 16, 16, __nv_bfloat16, wmma::col_major> bhi, blo;
                const int boff = (wn * 64 + fn * 16) * K1_LDA + kst * 16;
                wmma::load_matrix_sync(bhi, smA + K1_BHI + boff, K1_LDA);
                wmma::load_matrix_sync(blo, smA + K1_BLO + boff, K1_LDA);
#pragma unroll
                for (int im = 0; im < 2; im++) {
                    wmma::mma_sync(acc[im][fn], ahi[im], bhi, acc[im][fn]);
                    wmma::mma_sync(acc[im][fn], ahi[im], blo, acc[im][fn]);
                    wmma::mma_sync(acc[im][fn], alo[im], bhi, acc[im][fn]);
                }
            }
        }
        __syncthreads();
    }
#pragma unroll
    for (int im = 0; im < 2; im++)
#pragma unroll
        for (int fn = 0; fn < 4; fn++)
            wmma::store_matrix_sync(
                &g_h[(size_t)(m0 + wm * 32 + im * 16) * HF + n0 + wn * 64 + fn * 16],
                acc[im][fn], HF, wmma::mem_row_major);
}

// ------- K2: logit stats + row-scaled exp packs + fp16 h -------
__global__ __launch_bounds__(256) void k2_stats(const float* __restrict__ a_src,
                                                const float* __restrict__ a_dst) {
    const int gw   = (blockIdx.x * blockDim.x + threadIdx.x) >> 5;
    const int lane = threadIdx.x & 31;
    const int h    = gw & 3;
    const int bn   = gw >> 2;
    const float* hp = &g_h[(size_t)bn * HF + h * FF];
    const float v0 = hp[lane], v1 = hp[lane + 32];
    {
        const size_t o = (size_t)bn * HF + h * FF + lane;
        g_hf16[o]      = __float2half_rn(v0);
        g_hf16[o + 32] = __float2half_rn(v1);
    }
    float s = v0 * a_src[h * FF + lane] + v1 * a_src[h * FF + lane + 32];
    float d = v0 * a_dst[h * FF + lane] + v1 * a_dst[h * FF + lane + 32];
#pragma unroll
    for (int o = 16; o > 0; o >>= 1) {
        s += __shfl_xor_sync(0xffffffffu, s, o);
        d += __shfl_xor_sync(0xffffffffu, d, o);
    }
    if (lane == 0) {
        g_es[gw] = make_float4(s, expf(s), expf(0.2f * s), 0.f);
        // per-row scale c = max(d,0)+1 keeps fp16 numerators in [~e^-5, ~25];
        // softmax is invariant to per-row scaling (cancels in num/Z)
        const float c = fmaxf(d, 0.f) + 1.f;
        g_ed[gw] = make_float4(d, expf(d - c), expf(0.2f * d - c), 0.f);
    }
}

// ---- K3: fused masked softmax + aggregation, single-term fp16 wmma ----
// Phase 1 (scalar fp32): row-scaled numerators + exact fp32 Z -> fp16 A-matrix.
// Phase 2 (wmma fp16): warp w = (head=w>>1, ihalf=w&1): acc[32x64] += n[32x32]@h[32x64].
#define H_LD 264                     // 8*odd -> conflict-free ldmatrix rows
#define HBUF (TJ * H_LD)             // 8448 elems per h buffer
#define N_LD 40                      // 8*odd
#define NH   (64 * N_LD + 8)         // 2568 elems per-head stride (16B mult)
#define K3_H_OFF   0                 // 2 x 8448 fp16 = 33792 B
#define K3_ADJ_OFF 33792             // 2 x 64x36 f32 = 18432 B (epilogue scratch aliases here)
#define K3_ES_OFF  52224             // 2 x 128 float4 = 4096 B
#define K3_N_OFF   56320             // 4 x 2568 fp16 = 20544 B
#define K3_Z_OFF   76864             // 256 f32
#define K3_SMEM    77888

__global__ __launch_bounds__(256) void k3_agg(const float* __restrict__ adj,
                                              const float* __restrict__ bias,
                                              float* __restrict__ out) {
    extern __shared__ __align__(16) char sm3[];
    __half* hF16 = (__half*)(sm3 + K3_H_OFF);
    float*  adjS = (float*)(sm3 + K3_ADJ_OFF);
    float*  esS  = (float*)(sm3 + K3_ES_OFF);
    __half* nF16 = (__half*)(sm3 + K3_N_OFF);
    float*  zS   = (float*)(sm3 + K3_Z_OFF);

    const int t  = threadIdx.x;
    const int b  = blockIdx.y;
    const int i0 = blockIdx.x * TI;

    // phase-1 identity
    const int p_ii = t >> 2;
    const int p_h  = t & 3;
    const float4 Ed = g_ed[(size_t)(b * NN + i0 + p_ii) * HH + p_h];
    const float dvd = Ed.x, e1d = Ed.y, e2d = Ed.z;
    float z = 0.f;

    // phase-2 identity
    const int w     = t >> 5;
    const int lane  = t & 31;
    const int head  = w >> 1;
    const int ihalf = w & 1;
    wmma::fragment<wmma::accumulator, 16, 16, 16, float> acc[2][4];
#pragma unroll
    for (int im = 0; im < 2; im++)
#pragma unroll
        for (int fn = 0; fn < 4; fn++) wmma::fill_fragment(acc[im][fn], 0.f);

    // staging identities
    const int ar_r = t >> 2, ar_c = (t & 3) << 3;   // adj: 64 rows x 32 cols (2 chunks/thr)

    auto stage = [&](int jt, int bf) {
        const int j0 = jt * TJ;
        const size_t hb = (size_t)(b * NN + j0) * HF;
#pragma unroll
        for (int q = 0; q < 4; q++) {                // h: 32 rows x 256 fp16
            const int idx = (q << 8) + t;
            const int row = idx >> 5, ch = idx & 31;
            cpa16(sptr(hF16) + (bf * HBUF + row * H_LD + ch * 8) * 2,
                  g_hf16 + hb + row * HF + ch * 8);
        }
#pragma unroll
        for (int q = 0; q < 2; q++) {                // adj: 64 rows x 32 f32
            const int cc = ar_c + (q << 2);
            cpa16(sptr(adjS + bf * 2304 + ar_r * ADJ_ROW + cc),
                  &adj[(size_t)(b * NN + i0 + ar_r) * NN + j0 + cc]);
        }
        if (t < TJ * HH)                              // es: 128 float4
            cpa16(sptr(esS + bf * 512 + (t << 2)),
                  &g_es[(size_t)(b * NN + j0) * HH + t]);
    };

    stage(0, 0);
    cpa_commit();

    for (int jt = 0; jt < NJT; jt++) {
        const int cur = jt & 1;
        cpa_wait0();
        __syncthreads();   // tile jt visible; nF16 free (phase2 jt-1 done)

        if (jt + 1 < NJT) stage(jt + 1, cur ^ 1);
        cpa_commit();

        // phase 1: row-scaled numerators (exp factorized through LeakyReLU)
        {
            const float4* ap4 = (const float4*)(adjS + cur * 2304 + p_ii * ADJ_ROW);
            const float4* ep  = (const float4*)esS + cur * 128;
            __half* np = nF16 + p_h * NH + p_ii * N_LD;
#pragma unroll
            for (int j4 = 0; j4 < 8; j4++) {
                const float4 a = ap4[j4];
                float nv[4];
#pragma unroll
                for (int u = 0; u < 4; u++) {
                    const float4 E = ep[(((j4 << 2) + u) << 2) | p_h];
                    float v = (dvd + E.x >= 0.f) ? (e1d * E.y) : (e2d * E.z);
                    const float am = (u == 0) ? a.x : (u == 1) ? a.y : (u == 2) ? a.z : a.w;
                    v = (am > 0.5f) ? v : 0.f;
                    z += v;
                    nv[u] = v;
                }
                __half2 p01 = __floats2half2_rn(nv[0], nv[1]);
                __half2 p23 = __floats2half2_rn(nv[2], nv[3]);
                uint2 pk;
                pk.x = *reinterpret_cast<uint32_t*>(&p01);
                pk.y = *reinterpret_cast<uint32_t*>(&p23);
                *reinterpret_cast<uint2*>(np + (j4 << 2)) = pk;
            }
        }
        __syncthreads();   // n visible to consumer warps

        // phase 2: single fp16 wmma accumulation
        {
            const __half* hb = hF16 + cur * HBUF;
#pragma unroll
            for (int kst = 0; kst < 2; kst++) {
                wmma::fragment<wmma::matrix_a, 16, 16, 16, __half, wmma::row_major> a0, a1;
                const __half* ab = nF16 + head * NH + (ihalf * 32) * N_LD + kst * 16;
                wmma::load_matrix_sync(a0, ab, N_LD);
                wmma::load_matrix_sync(a1, ab + 16 * N_LD, N_LD);
#pragma unroll
                for (int fn = 0; fn < 4; fn++) {
                    wmma::fragment<wmma::matrix_b, 16, 16, 16, __half, wmma::row_major> bf_;
                    wmma::load_matrix_sync(bf_, hb + (kst * 16) * H_LD + head * 64 + fn * 16, H_LD);
                    wmma::mma_sync(acc[0][fn], a0, bf_, acc[0][fn]);
                    wmma::mma_sync(acc[1][fn], a1, bf_, acc[1][fn]);
                }
            }
        }
    }

    zS[(p_ii << 2) | p_h] = z;
    __syncthreads();       // also retires adj/es buffers -> scratch alias safe

    // epilogue: frag -> per-warp scratch (aliased over adjS) -> /Z + bias -> gmem
    float* scr = (float*)(sm3 + K3_ADJ_OFF) + w * 320;
#pragma unroll
    for (int im = 0; im < 2; im++) {
#pragma unroll
        for (int fn = 0; fn < 4; fn++) {
            wmma::store_matrix_sync(scr, acc[im][fn], 20, wmma::mem_row_major);
            __syncwarp();
#pragma unroll
            for (int e = 0; e < 8; e++) {
                const int idx = lane + (e << 5);
                const int row = idx >> 4, col = idx & 15;
                const int ii  = ihalf * 32 + im * 16 + row;
                const int c   = head * 64 + fn * 16 + col;
                const float rz = 1.f / zS[(ii << 2) | head];
                out[(size_t)(b * NN + i0 + ii) * HF + c] =
                    scr[row * 20 + col] * rz + bias[c];
            }
            __syncwarp();
        }
    }
}

extern "C" void kernel_launch(void* const* d_in, const int* in_sizes, int n_in,
                              void* d_out, int out_size) {
    const float* x     = (const float*)d_in[0];
    const float* adj   = (const float*)d_in[1];
    const float* Wm    = (const float*)d_in[2];
    const float* a_src = (const float*)d_in[3];
    const float* a_dst = (const float*)d_in[4];
    const float* bias  = (const float*)d_in[5];
    float* out = (float*)d_out;

    cudaFuncSetAttribute(k1_mma, cudaFuncAttributeMaxDynamicSharedMemorySize, K1_SMEM);
    cudaFuncSetAttribute(k3_agg, cudaFuncAttributeMaxDynamicSharedMemorySize, K3_SMEM);

    k0_split_x<<<(BB * NN * DD) / 4 / 256, 256>>>(x);
    k0_split_w<<<(DD * HF) / 256, 256>>>(Wm);
    k1_mma<<<dim3(HF / 128, (BB * NN) / 128), 256, K1_SMEM>>>();
    k2_stats<<<(BB * NN * HH) / 8, 256>>>(a_src, a_dst);
    k3_agg<<<dim3(NN / TI, BB), 256, K3_SMEM>>>(adj, bias, out);
}